// round 10
// baseline (speedup 1.0000x reference)
#include <cuda_runtime.h>
#include <cstdint>

// KVCacheManager update_cache, token-gen path.
//   L=2, B=4, H=8, M=4096, D=128, fp32
//   out shape: (2[kv], L, B, H, M, D)
//   out[kv,l,b,h,m,d] = (m == pos[b] && pos[b] < seq_len) ? latest[l,b,h,d]
//                                                         : cache[l,b,h,m,d]
//
// HBM-bound streaming copy with fused point-scatter.
// R6: 256-bit (v8.f32) loads/stores — PTX 8.7 / sm_100+. Halves wavefront
// count and doubles contiguous burst per request stream.
//
// v8-chunk linear index (23 bits = 8,388,608 chunks of 8 floats):
//   d8 : bits [0:4)   (16 v8-chunks per D=128 row)
//   m  : bits [4:16)  (4096)
//   h  : bits [16:19) (8)
//   b  : bits [19:21) (4)
//   l  : bit  [21]    (2)
//   kv : bit  [22]    (2)
//
// History: R2 75.84us/DRAM80.7 (best struct) ; R3 hints+layout 76.7 ;
//          R4 copy-engine 88 ; R5 stcs-only 75.58 (neutral).

static constexpr unsigned TOTAL_V8  = 1u << 23;        // 8,388,608 chunks
static constexpr unsigned HALF_MASK = (1u << 22) - 1;  // within one cache
static constexpr unsigned THREADS   = 256;
static constexpr unsigned VPT       = 2;               // v8 chunks per thread
static constexpr unsigned GRID      = TOTAL_V8 / (THREADS * VPT); // 16384

struct __align__(32) f8 { float v[8]; };

__device__ __forceinline__ f8 ldg256(const f8* p)
{
    f8 r;
    asm volatile("ld.global.nc.v8.f32 {%0,%1,%2,%3,%4,%5,%6,%7}, [%8];"
                 : "=f"(r.v[0]), "=f"(r.v[1]), "=f"(r.v[2]), "=f"(r.v[3]),
                   "=f"(r.v[4]), "=f"(r.v[5]), "=f"(r.v[6]), "=f"(r.v[7])
                 : "l"(p));
    return r;
}

__device__ __forceinline__ void stg256(f8* p, const f8& r)
{
    asm volatile("st.global.v8.f32 [%0], {%1,%2,%3,%4,%5,%6,%7,%8};"
                 :: "l"(p),
                    "f"(r.v[0]), "f"(r.v[1]), "f"(r.v[2]), "f"(r.v[3]),
                    "f"(r.v[4]), "f"(r.v[5]), "f"(r.v[6]), "f"(r.v[7])
                 : "memory");
}

__device__ __forceinline__ f8 load_elem(
    unsigned j,
    const f8* __restrict__ k_cache,
    const f8* __restrict__ v_cache,
    const f8* __restrict__ latest_k,
    const f8* __restrict__ latest_v,
    const int* __restrict__ pos, int S)
{
    unsigned d8 = j & 15u;
    unsigned m  = (j >> 4)  & 4095u;
    unsigned h  = (j >> 16) & 7u;
    unsigned b  = (j >> 19) & 3u;
    unsigned l  = (j >> 21) & 1u;
    unsigned kv = (j >> 22) & 1u;
    unsigned ci = j & HALF_MASK;

    int p = __ldg(&pos[b]);
    if ((int)m == p && p < S) {
        // latest_{k,v}: (L,B,H,1,D) -> v8 index ((l*B+b)*H+h)*16 + d8
        unsigned li = ((((l << 2) + b) << 3) + h) * 16u + d8;
        return kv ? ldg256(&latest_v[li]) : ldg256(&latest_k[li]);
    }
    return kv ? ldg256(&v_cache[ci]) : ldg256(&k_cache[ci]);
}

__global__ void __launch_bounds__(THREADS)
kv_update_kernel(const f8* __restrict__ k_cache,
                 const f8* __restrict__ v_cache,
                 const f8* __restrict__ latest_k,
                 const f8* __restrict__ latest_v,
                 const int* __restrict__ pos,
                 const int* __restrict__ seq_len_p,
                 f8*        __restrict__ out)
{
    const unsigned span = GRID * THREADS;   // 4,194,304
    unsigned j0 = blockIdx.x * THREADS + threadIdx.x;
    unsigned j1 = j0 + span;

    int S = seq_len_p ? __ldg(seq_len_p) : 4096;

    f8 v0 = load_elem(j0, k_cache, v_cache, latest_k, latest_v, pos, S);
    f8 v1 = load_elem(j1, k_cache, v_cache, latest_k, latest_v, pos, S);
    stg256(&out[j0], v0);
    stg256(&out[j1], v1);
}

extern "C" void kernel_launch(void* const* d_in, const int* in_sizes, int n_in,
                              void* d_out, int out_size)
{
    // metadata order: k_caches, v_caches, latest_k, latest_v, position_ids, seq_len
    const f8* k_cache  = (const f8*)d_in[0];
    const f8* v_cache  = (const f8*)d_in[1];
    const f8* latest_k = (const f8*)d_in[2];
    const f8* latest_v = (const f8*)d_in[3];
    const int* pos     = (const int*)d_in[4];
    const int* seq_len = (n_in >= 6) ? (const int*)d_in[5] : nullptr;
    f8* out = (f8*)d_out;

    kv_update_kernel<<<GRID, THREADS>>>(k_cache, v_cache, latest_k, latest_v,
                                        pos, seq_len, out);
    (void)in_sizes; (void)out_size;
}